// round 3
// baseline (speedup 1.0000x reference)
#include <cuda_runtime.h>
#include <math.h>

// Problem dims
#define BB 16
#define LL 1024
#define HH 8
#define EE 64
#define DD 512    // H*E
#define C2 1024   // 2*d
#define LF 513    // L/2+1
#define NROW (BB*DD)   // 8192 sequences per tensor

// -------- scratch (device globals; no allocations allowed) --------
__device__ float  g_y [BB * C2 * LL];         // conv output [b][c][l]
__device__ float2 g_qf[NROW * LF];
__device__ float2 g_kf[NROW * LF];
__device__ float2 g_vf[NROW * LF];
__device__ float2 g_of[NROW * LF];

// ======================================================================
// Kernel 1: conv1d as GEMM, per batch: y[c][l] = bias[c] + sum_kk W[c][kk]*X[kk][l]
//   kk = t*512 + ci ;  X[kk][l] = q[b][l + t - 1][ci]   (zero padded)
//   W layout: [c][ci][t]  (c-major, 1536 per c)
// grid (L/64, C2/64, B), 256 threads, 64x64 tile, 4x4 micro
// ======================================================================
__global__ void __launch_bounds__(256) conv_kernel(const float* __restrict__ q,
                                                   const float* __restrict__ W,
                                                   const float* __restrict__ bias)
{
    __shared__ float As[16][64];
    __shared__ float Bs[16][68];   // padded row

    const int b  = blockIdx.z;
    const int c0 = blockIdx.y * 64;
    const int l0 = blockIdx.x * 64;
    const int t  = threadIdx.x;
    const int tc = (t & 15) * 4;
    const int tl = (t >> 4) * 4;

    float acc[4][4] = {};
    const float* qb = q + (size_t)b * (LL * DD);

    for (int kt = 0; kt < 96; kt++) {
        const int kk0 = kt * 16;
        const int tt  = kk0 >> 9;       // conv tap 0..2 (constant within k-tile)
        const int ci0 = kk0 & 511;

        // load As[k][c] directly from W[c][ci][t]: As[k][c] = W[(c0+c)*1536 + (ci0+k)*3 + tt]
        #pragma unroll
        for (int r = 0; r < 4; r++) {
            int idx = t + r * 256;
            int k = idx >> 6, c = idx & 63;
            As[k][c] = W[(size_t)(c0 + c) * 1536 + (ci0 + k) * 3 + tt];
        }
        // load Bs[k][l]  (16-float coalesced rows from q)
        #pragma unroll
        for (int r = 0; r < 4; r++) {
            int idx = t + r * 256;
            int k = idx & 15, l = idx >> 4;
            int lg = l0 + l + tt - 1;
            Bs[k][l] = (lg >= 0 && lg < LL) ? qb[(size_t)lg * DD + ci0 + k] : 0.f;
        }
        __syncthreads();

        #pragma unroll
        for (int k = 0; k < 16; k++) {
            float4 av = *reinterpret_cast<const float4*>(&As[k][tc]);
            float4 bv = *reinterpret_cast<const float4*>(&Bs[k][tl]);
            float a4[4] = {av.x, av.y, av.z, av.w};
            float b4[4] = {bv.x, bv.y, bv.z, bv.w};
            #pragma unroll
            for (int i = 0; i < 4; i++)
                #pragma unroll
                for (int j = 0; j < 4; j++)
                    acc[i][j] = fmaf(a4[i], b4[j], acc[i][j]);
        }
        __syncthreads();
    }

    float* yb = g_y + (size_t)b * (C2 * LL);
    #pragma unroll
    for (int i = 0; i < 4; i++) {
        int c = c0 + tc + i;
        float bi = bias[c];
        float4 o = make_float4(acc[i][0] + bi, acc[i][1] + bi,
                               acc[i][2] + bi, acc[i][3] + bi);
        *reinterpret_cast<float4*>(&yb[(size_t)c * LL + l0 + tl]) = o;
    }
}

// ======================================================================
// Stockham radix-2 1024-pt FFT in shared memory (DIF, auto-sorting).
// 256 threads, 2 butterflies each per stage, 10 stages. Result ends in sa.
// sign = -1 forward, +1 inverse (unscaled).
// ======================================================================
__device__ __forceinline__ void fft1024(float2* sa, float2* sb, int tid, float sign)
{
    float2* src = sa;
    float2* dst = sb;
    int n = 1024, s = 1, logs = 0;
    #pragma unroll 1
    for (int st = 0; st < 10; st++) {
        const int m = n >> 1;
        const float w0 = sign * 6.28318530717958647692f / (float)n;
        #pragma unroll
        for (int i = tid; i < 512; i += 256) {
            int q = i & (s - 1);
            int p = i >> logs;
            float2 a = src[q + s * p];
            float2 b = src[q + s * (p + m)];
            float sn, cs;
            __sincosf(w0 * (float)p, &sn, &cs);
            float2 d0 = make_float2(a.x + b.x, a.y + b.y);
            float tx = a.x - b.x, ty = a.y - b.y;
            float2 d1 = make_float2(tx * cs - ty * sn, tx * sn + ty * cs);
            dst[q + s * (2 * p)]     = d0;
            dst[q + s * (2 * p + 1)] = d1;
        }
        __syncthreads();
        float2* tmp = src; src = dst; dst = tmp;
        n >>= 1; s <<= 1; logs++;
    }
    // 10 swaps (even): final data is in sa
}

// ======================================================================
// Kernel 2: GLU + rfft of q2.  grid = 8192 rows (row = b*512 + h*64 + e)
// q2[l] = a[l] * sigmoid(g[l]);  a = y[b][c][:], g = y[b][c+512][:]
// out: g_qf[row][0..512] * (1/32)  (ortho)
// ======================================================================
__global__ void __launch_bounds__(256) fft_q_kernel()
{
    __shared__ float2 sa[1024];
    __shared__ float2 sb[1024];
    const int row = blockIdx.x;
    const int b = row >> 9, c = row & 511;
    const int tid = threadIdx.x;
    const float* ya = g_y + ((size_t)b * C2 + c) * LL;
    const float* yg = ya + (size_t)DD * LL;

    for (int l = tid; l < 1024; l += 256) {
        float a = ya[l], g = yg[l];
        float v = a / (1.f + __expf(-g));
        sa[l] = make_float2(v, 0.f);
    }
    __syncthreads();
    fft1024(sa, sb, tid, -1.f);

    float2* out = g_qf + (size_t)row * LF;
    const float sc = 0.03125f;  // 1/sqrt(1024)
    for (int x = tid; x < LF; x += 256)
        out[x] = make_float2(sa[x].x * sc, sa[x].y * sc);
}

// ======================================================================
// Kernel 3: rfft of k and v (strided gather). grid (8192, 2)
// src[b][s][h][e] -> row (b*512 + h*64 + e), element stride 512
// ======================================================================
__global__ void __launch_bounds__(256) fft_kv_kernel(const float* __restrict__ kin,
                                                     const float* __restrict__ vin)
{
    __shared__ float2 sa[1024];
    __shared__ float2 sb[1024];
    const int row = blockIdx.x;
    const int which = blockIdx.y;
    const int b = row >> 9, c = row & 511;
    const int tid = threadIdx.x;
    const float* base = (which ? vin : kin) + (size_t)b * (LL * DD) + c;

    for (int s = tid; s < 1024; s += 256)
        sa[s] = make_float2(base[(size_t)s * DD], 0.f);
    __syncthreads();
    fft1024(sa, sb, tid, -1.f);

    float2* out = (which ? g_vf : g_kf) + (size_t)row * LF;
    const float sc = 0.03125f;
    for (int x = tid; x < LF; x += 256)
        out[x] = make_float2(sa[x].x * sc, sa[x].y * sc);
}

// ======================================================================
// Kernel 4: streamed complex attention.
//   s[x,y]  = (1/8) sum_e qf[e,x] * conj(kf[e,y])
//   w       = 1 + sigmoid(|s|)
//   rowsum[x] += |s| * w   ;  O[e,x] += sum_y (s*w) * vf[e,y]
//   of[e,x] = O[e,x] / max(rowsum[x], 1e-12)
// grid (ceil(513/32)=17, B*H=128), 256 threads
// ======================================================================
#define XT 32
#define YT 32

__global__ void __launch_bounds__(256) attn_kernel()
{
    __shared__ float2 qt[EE][XT];        // 16 KB, q tile (prescaled by 1/8)
    __shared__ float2 kv[EE][YT];        // 16 KB, reused: kf then vf
    __shared__ float2 sw[YT][XT + 1];    // weighted scores [y][x], padded
    __shared__ float  rsum[XT];

    const int bh = blockIdx.y;                 // 0..127
    const int x0 = blockIdx.x * XT;            // 0..512
    const int t  = threadIdx.x;
    const int rowbase = bh * EE;

    // load q tile
    for (int idx = t; idx < EE * XT; idx += 256) {
        int e = idx >> 5, x = idx & 31;
        float2 v = make_float2(0.f, 0.f);
        if (x0 + x < LF) {
            v = g_qf[(size_t)(rowbase + e) * LF + x0 + x];
            v.x *= 0.125f; v.y *= 0.125f;
        }
        qt[e][x] = v;
    }
    if (t < XT) rsum[t] = 0.f;

    // O accumulators: thread owns e = eb..eb+7, x = t&31
    const int xo = t & 31;
    const int eb = (t >> 5) * 8;
    float2 O[8];
    #pragma unroll
    for (int i = 0; i < 8; i++) O[i] = make_float2(0.f, 0.f);

    // s-phase mapping: y = t&31, rows xb..xb+3 owned by warp (t>>5)
    const int ys = t & 31;
    const int xb = (t >> 5) * 4;
    const int lane = t & 31;

    __syncthreads();

    for (int y0 = 0; y0 < LF; y0 += YT) {
        // ---- load kf tile ----
        for (int idx = t; idx < EE * YT; idx += 256) {
            int e = idx >> 5, y = idx & 31;
            kv[e][y] = (y0 + y < LF) ? g_kf[(size_t)(rowbase + e) * LF + y0 + y]
                                     : make_float2(0.f, 0.f);
        }
        __syncthreads();

        // ---- s = q . conj(k), then weight ----
        float2 acc[4];
        #pragma unroll
        for (int i = 0; i < 4; i++) acc[i] = make_float2(0.f, 0.f);
        #pragma unroll 4
        for (int e = 0; e < EE; e++) {
            float2 kk = kv[e][ys];
            #pragma unroll
            for (int i = 0; i < 4; i++) {
                float2 qq = qt[e][xb + i];
                acc[i].x += qq.x * kk.x + qq.y * kk.y;
                acc[i].y += qq.y * kk.x - qq.x * kk.y;
            }
        }
        #pragma unroll
        for (int i = 0; i < 4; i++) {
            float m = sqrtf(acc[i].x * acc[i].x + acc[i].y * acc[i].y);
            float w = 1.f + 1.f / (1.f + __expf(-m));
            sw[ys][xb + i] = make_float2(acc[i].x * w, acc[i].y * w);
            float v = m * w;
            // warp-sum over y (lanes of this warp)
            #pragma unroll
            for (int off = 16; off > 0; off >>= 1)
                v += __shfl_xor_sync(0xffffffffu, v, off);
            if (lane == 0) rsum[xb + i] += v;
        }
        __syncthreads();

        // ---- load vf tile into same buffer ----
        for (int idx = t; idx < EE * YT; idx += 256) {
            int e = idx >> 5, y = idx & 31;
            kv[e][y] = (y0 + y < LF) ? g_vf[(size_t)(rowbase + e) * LF + y0 + y]
                                     : make_float2(0.f, 0.f);
        }
        __syncthreads();

        // ---- O += sw * vf ----
        #pragma unroll 4
        for (int y = 0; y < YT; y++) {
            float2 s = sw[y][xo];
            #pragma unroll
            for (int i = 0; i < 8; i++) {
                float2 vv = kv[eb + i][y];
                O[i].x += s.x * vv.x - s.y * vv.y;
                O[i].y += s.x * vv.y + s.y * vv.x;
            }
        }
        __syncthreads();
    }

    // ---- normalize + write ----
    const int xg = x0 + xo;
    if (xg < LF) {
        float inv = 1.f / fmaxf(rsum[xo], 1e-12f);
        #pragma unroll
        for (int i = 0; i < 8; i++)
            g_of[(size_t)(rowbase + eb + i) * LF + xg] =
                make_float2(O[i].x * inv, O[i].y * inv);
    }
}

// ======================================================================
// Kernel 5: irfft (ortho) + scatter to [B,L,H,E]. grid = 8192 rows.
// Mirror to full spectrum (conj symmetry), inverse FFT, Re(.)/32.
// ======================================================================
__global__ void __launch_bounds__(256) ifft_kernel(float* __restrict__ out)
{
    __shared__ float2 sa[1024];
    __shared__ float2 sb[1024];
    const int row = blockIdx.x;
    const int b = row >> 9, c = row & 511;
    const int tid = threadIdx.x;
    const float2* src = g_of + (size_t)row * LF;

    for (int n = tid; n < 1024; n += 256) {
        if (n <= 512) sa[n] = src[n];
        else {
            float2 v = src[1024 - n];
            sa[n] = make_float2(v.x, -v.y);
        }
    }
    __syncthreads();
    fft1024(sa, sb, tid, +1.f);

    float* dst = out + (size_t)b * (LL * DD) + c;
    const float sc = 0.03125f;
    for (int l = tid; l < 1024; l += 256)
        dst[(size_t)l * DD] = sa[l].x * sc;
}

// ======================================================================
// launch
// ======================================================================
extern "C" void kernel_launch(void* const* d_in, const int* in_sizes, int n_in,
                              void* d_out, int out_size)
{
    const float* q    = (const float*)d_in[0];
    const float* k    = (const float*)d_in[1];
    const float* v    = (const float*)d_in[2];
    const float* W    = (const float*)d_in[3];
    const float* bias = (const float*)d_in[4];
    float* out = (float*)d_out;

    dim3 cg(LL / 64, C2 / 64, BB);
    conv_kernel<<<cg, 256>>>(q, W, bias);

    fft_q_kernel<<<NROW, 256>>>();
    fft_kv_kernel<<<dim3(NROW, 2), 256>>>(k, v);

    attn_kernel<<<dim3((LF + XT - 1) / XT, BB * HH), 256>>>();

    ifft_kernel<<<NROW, 256>>>(out);
}

// round 4
// speedup vs baseline: 1.7169x; 1.7169x over previous
#include <cuda_runtime.h>
#include <math.h>

// Problem dims
#define BB 16
#define LL 1024
#define HH 8
#define EE 64
#define DD 512    // H*E
#define C2 1024   // 2*d
#define LF 513    // L/2+1
#define NROW (BB*DD)   // 8192 sequences per tensor

typedef unsigned long long ull;

// -------- packed f32x2 helpers --------
__device__ __forceinline__ ull& U64(float2& v) { return *reinterpret_cast<ull*>(&v); }
__device__ __forceinline__ ull  LD64(const float2* p) { return *reinterpret_cast<const ull*>(p); }
__device__ __forceinline__ ull  bcast2(float s) {
    ull r; asm("mov.b64 %0, {%1,%2};" : "=l"(r) : "f"(s), "f"(s)); return r;
}
// acc (float2) += a * b  elementwise, single FFMA2
#define FFMA2ACC(acc, a, b) \
    asm("fma.rn.f32x2 %0, %1, %2, %0;" : "+l"(U64(acc)) : "l"(a), "l"(b))

__device__ __forceinline__ float2 fadd2(float2 a, float2 b) {
    float2 d;
    asm("add.rn.f32x2 %0, %1, %2;" : "=l"(U64(d)) : "l"(U64(a)), "l"(U64(b)));
    return d;
}
__device__ __forceinline__ float2 cmulf(float2 a, float2 b) {
    return make_float2(a.x * b.x - a.y * b.y, a.x * b.y + a.y * b.x);
}

// -------- scratch (device globals; no allocations allowed) --------
__device__ float  g_Wt[1536 * 1024];          // W transposed to [kk][c]
__device__ float  g_y [BB * C2 * LL];         // conv output [b][c][l]
__device__ float2 g_qf[NROW * LF];
__device__ float2 g_kf[NROW * LF];
__device__ float2 g_vf[NROW * LF];
__device__ float2 g_of[NROW * LF];

// ======================================================================
// Kernel 0: transpose W[c][ci][t] -> Wt[kk][c], kk = t*512 + ci
// ======================================================================
__global__ void __launch_bounds__(256) wtrans_kernel(const float* __restrict__ W)
{
    int idx = blockIdx.x * 256 + threadIdx.x;
    if (idx < 1536 * 1024) {
        int kk = idx >> 10;
        int c  = idx & 1023;
        g_Wt[idx] = W[(size_t)c * 1536 + (kk & 511) * 3 + (kk >> 9)];
    }
}

// ======================================================================
// Kernel 1: conv1d as GEMM: y[c][l] = bias[c] + sum_kk Wt[kk][c]*X[kk][l]
//   X[kk][l] = q[b][l + (kk>>9) - 1][kk&511]   (zero padded)
// grid (L/128, C2/128, B), 256 threads, 128x128 tile, 8x8 micro, FFMA2
// ======================================================================
__global__ void __launch_bounds__(256) conv_kernel(const float* __restrict__ q,
                                                   const float* __restrict__ bias)
{
    __shared__ float As[16][128];
    __shared__ float Bs[16][132];

    const int b  = blockIdx.z;
    const int c0 = blockIdx.y * 128;
    const int l0 = blockIdx.x * 128;
    const int t  = threadIdx.x;
    const int tc = (t & 15) * 8;
    const int tl = (t >> 4) * 8;

    float2 acc[8][4] = {};   // acc[i][jp] packs (l-pair) outputs for c-row i
    const float* qb = q + (size_t)b * (LL * DD);

    for (int kt = 0; kt < 96; kt++) {
        const int kk0 = kt * 16;
        const int tt  = kk0 >> 9;       // conv tap 0..2 (constant within k-tile)
        const int ci0 = kk0 & 511;

        // As[k][c] from Wt (coalesced 128-float rows)
        #pragma unroll
        for (int r = 0; r < 8; r++) {
            int idx = t + r * 256;
            int k = idx >> 7, c = idx & 127;
            As[k][c] = g_Wt[(size_t)(kk0 + k) * 1024 + c0 + c];
        }
        // Bs[k][l] from q (16-float coalesced segments)
        #pragma unroll
        for (int r = 0; r < 8; r++) {
            int idx = t + r * 256;
            int k = idx & 15, l = idx >> 4;
            int lg = l0 + l + tt - 1;
            Bs[k][l] = (lg >= 0 && lg < LL) ? qb[(size_t)lg * DD + ci0 + k] : 0.f;
        }
        __syncthreads();

        #pragma unroll
        for (int k = 0; k < 16; k++) {
            float4 a0 = *reinterpret_cast<const float4*>(&As[k][tc]);
            float4 a1 = *reinterpret_cast<const float4*>(&As[k][tc + 4]);
            float4 b0 = *reinterpret_cast<const float4*>(&Bs[k][tl]);
            float4 b1 = *reinterpret_cast<const float4*>(&Bs[k][tl + 4]);
            float2 bb[4] = { make_float2(b0.x, b0.y), make_float2(b0.z, b0.w),
                             make_float2(b1.x, b1.y), make_float2(b1.z, b1.w) };
            ull bp[4];
            #pragma unroll
            for (int j = 0; j < 4; j++) bp[j] = U64(bb[j]);
            float aa[8] = { a0.x, a0.y, a0.z, a0.w, a1.x, a1.y, a1.z, a1.w };
            #pragma unroll
            for (int i = 0; i < 8; i++) {
                ull ad = bcast2(aa[i]);
                #pragma unroll
                for (int j = 0; j < 4; j++)
                    FFMA2ACC(acc[i][j], ad, bp[j]);
            }
        }
        __syncthreads();
    }

    float* yb = g_y + (size_t)b * (C2 * LL);
    #pragma unroll
    for (int i = 0; i < 8; i++) {
        int c = c0 + tc + i;
        float bi = bias[c];
        float4 o0 = make_float4(acc[i][0].x + bi, acc[i][0].y + bi,
                                acc[i][1].x + bi, acc[i][1].y + bi);
        float4 o1 = make_float4(acc[i][2].x + bi, acc[i][2].y + bi,
                                acc[i][3].x + bi, acc[i][3].y + bi);
        *reinterpret_cast<float4*>(&yb[(size_t)c * LL + l0 + tl])     = o0;
        *reinterpret_cast<float4*>(&yb[(size_t)c * LL + l0 + tl + 4]) = o1;
    }
}

// ======================================================================
// Stockham radix-4 1024-pt FFT in shared memory (DIF, auto-sorting).
// 256 threads, ONE radix-4 butterfly per thread per stage, 5 stages.
// sign = -1 forward, +1 inverse (unscaled). Returns pointer to result.
// ======================================================================
__device__ __forceinline__ float2* fft1024_r4(float2* sa, float2* sb, int tid, float sign)
{
    float2* src = sa;
    float2* dst = sb;
    int n = 1024, s = 1, logs = 0;
    #pragma unroll
    for (int st = 0; st < 5; st++) {
        const int m = n >> 2;
        const int qq = tid & (s - 1);
        const int p  = tid >> logs;
        float2 a0 = src[qq + s * p];
        float2 a1 = src[qq + s * (p + m)];
        float2 a2 = src[qq + s * (p + 2 * m)];
        float2 a3 = src[qq + s * (p + 3 * m)];

        float2 t0 = fadd2(a0, a2);
        float2 t2 = make_float2(a0.x - a2.x, a0.y - a2.y);
        float2 t1 = fadd2(a1, a3);
        float2 t3 = make_float2(a1.x - a3.x, a1.y - a3.y);
        float2 it3 = make_float2(-sign * t3.y, sign * t3.x);

        float2 c0 = fadd2(t0, t1);
        float2 c2 = make_float2(t0.x - t1.x, t0.y - t1.y);
        float2 c1 = fadd2(t2, it3);
        float2 c3 = make_float2(t2.x - it3.x, t2.y - it3.y);

        float ang = sign * 6.28318530717958647692f * (float)p / (float)n;
        float sn, cs; __sincosf(ang, &sn, &cs);
        float2 w1 = make_float2(cs, sn);
        float2 w2 = make_float2(cs * cs - sn * sn, 2.f * cs * sn);
        float2 w3 = cmulf(w1, w2);

        int ob = qq + s * 4 * p;
        dst[ob]         = c0;
        dst[ob + s]     = cmulf(c1, w1);
        dst[ob + 2 * s] = cmulf(c2, w2);
        dst[ob + 3 * s] = cmulf(c3, w3);
        __syncthreads();
        float2* tmp = src; src = dst; dst = tmp;
        n >>= 2; s <<= 2; logs += 2;
    }
    return src;   // after final swap, src points at the last-written buffer
}

// ======================================================================
// Kernel 2: GLU + rfft of q2.  grid = 8192 rows (row = b*512 + c)
// ======================================================================
__global__ void __launch_bounds__(256) fft_q_kernel()
{
    __shared__ float2 sa[1024];
    __shared__ float2 sb[1024];
    const int row = blockIdx.x;
    const int b = row >> 9, c = row & 511;
    const int tid = threadIdx.x;
    const float* ya = g_y + ((size_t)b * C2 + c) * LL;
    const float* yg = ya + (size_t)DD * LL;

    for (int l = tid; l < 1024; l += 256) {
        float a = ya[l], g = yg[l];
        float v = a / (1.f + __expf(-g));
        sa[l] = make_float2(v, 0.f);
    }
    __syncthreads();
    float2* res = fft1024_r4(sa, sb, tid, -1.f);

    float2* out = g_qf + (size_t)row * LF;
    const float sc = 0.03125f;  // 1/sqrt(1024)
    for (int x = tid; x < LF; x += 256)
        out[x] = make_float2(res[x].x * sc, res[x].y * sc);
}

// ======================================================================
// Kernel 3: rfft of k and v (strided gather). grid (8192, 2)
// ======================================================================
__global__ void __launch_bounds__(256) fft_kv_kernel(const float* __restrict__ kin,
                                                     const float* __restrict__ vin)
{
    __shared__ float2 sa[1024];
    __shared__ float2 sb[1024];
    const int row = blockIdx.x;
    const int which = blockIdx.y;
    const int b = row >> 9, c = row & 511;
    const int tid = threadIdx.x;
    const float* base = (which ? vin : kin) + (size_t)b * (LL * DD) + c;

    for (int s = tid; s < 1024; s += 256)
        sa[s] = make_float2(base[(size_t)s * DD], 0.f);
    __syncthreads();
    float2* res = fft1024_r4(sa, sb, tid, -1.f);

    float2* out = (which ? g_vf : g_kf) + (size_t)row * LF;
    const float sc = 0.03125f;
    for (int x = tid; x < LF; x += 256)
        out[x] = make_float2(res[x].x * sc, res[x].y * sc);
}

// ======================================================================
// Kernel 4: streamed complex attention with packed f32x2 math.
//   s[x,y]  = (1/8) sum_e qf[e,x] * conj(kf[e,y])
//   w       = 1 + sigmoid(|s|);  rowsum[x] += |s|*w
//   O[e,x] += sum_y (s*w) * vf[e,y];  of = O / max(rowsum,1e-12)
// grid (17, B*H=128), 256 threads
// ======================================================================
#define XT 32
#define YT 32

__global__ void __launch_bounds__(256) attn_kernel()
{
    __shared__ float2 qt[EE][XT];        // 16 KB, q tile (prescaled by 1/8)
    __shared__ float2 kv[EE][YT];        // 16 KB, reused: kf then vf
    __shared__ float2 sw[YT][XT + 1];    // weighted scores [y][x], padded
    __shared__ float  rsum[XT];

    const int bh = blockIdx.y;
    const int x0 = blockIdx.x * XT;
    const int t  = threadIdx.x;
    const int rowbase = bh * EE;

    for (int idx = t; idx < EE * XT; idx += 256) {
        int e = idx >> 5, x = idx & 31;
        float2 v = make_float2(0.f, 0.f);
        if (x0 + x < LF) {
            v = g_qf[(size_t)(rowbase + e) * LF + x0 + x];
            v.x *= 0.125f; v.y *= 0.125f;
        }
        qt[e][x] = v;
    }
    if (t < XT) rsum[t] = 0.f;

    const int xo   = t & 31;          // O-phase x / sw column / y in vv loads
    const int eb   = (t >> 5) * 8;    // O-phase e block
    const int ys   = t & 31;          // s-phase y
    const int xb   = (t >> 5) * 4;    // s-phase x block (mult of 4)
    const int lane = t & 31;

    float2 OP[8], OQ[8];
    #pragma unroll
    for (int i = 0; i < 8; i++) { OP[i] = make_float2(0.f, 0.f); OQ[i] = make_float2(0.f, 0.f); }

    __syncthreads();

    for (int y0 = 0; y0 < LF; y0 += YT) {
        // ---- load kf tile ----
        for (int idx = t; idx < EE * YT; idx += 256) {
            int e = idx >> 5, y = idx & 31;
            kv[e][y] = (y0 + y < LF) ? g_kf[(size_t)(rowbase + e) * LF + y0 + y]
                                     : make_float2(0.f, 0.f);
        }
        __syncthreads();

        // ---- s-phase: P += q*kx, Q += q*ky (packed) ----
        float2 SP[4], SQ[4];
        #pragma unroll
        for (int i = 0; i < 4; i++) { SP[i] = make_float2(0.f, 0.f); SQ[i] = make_float2(0.f, 0.f); }

        #pragma unroll 8
        for (int e = 0; e < EE; e++) {
            float2 kk = kv[e][ys];
            ull kxx = bcast2(kk.x);
            ull kyy = bcast2(kk.y);
            const float4* qp = reinterpret_cast<const float4*>(&qt[e][xb]);
            float4 qA = qp[0];
            float4 qB = qp[1];
            float2 q0 = make_float2(qA.x, qA.y), q1 = make_float2(qA.z, qA.w);
            float2 q2 = make_float2(qB.x, qB.y), q3 = make_float2(qB.z, qB.w);
            FFMA2ACC(SP[0], U64(q0), kxx);  FFMA2ACC(SQ[0], U64(q0), kyy);
            FFMA2ACC(SP[1], U64(q1), kxx);  FFMA2ACC(SQ[1], U64(q1), kyy);
            FFMA2ACC(SP[2], U64(q2), kxx);  FFMA2ACC(SQ[2], U64(q2), kyy);
            FFMA2ACC(SP[3], U64(q3), kxx);  FFMA2ACC(SQ[3], U64(q3), kyy);
        }
        #pragma unroll
        for (int i = 0; i < 4; i++) {
            float re = SP[i].x + SQ[i].y;      // qx*kx + qy*ky
            float im = SP[i].y - SQ[i].x;      // qy*kx - qx*ky
            float m  = sqrtf(re * re + im * im);
            float w  = 1.f + 1.f / (1.f + __expf(-m));
            sw[ys][xb + i] = make_float2(re * w, im * w);
            float v = m * w;
            #pragma unroll
            for (int off = 16; off > 0; off >>= 1)
                v += __shfl_xor_sync(0xffffffffu, v, off);
            if (lane == 0) rsum[xb + i] += v;
        }
        __syncthreads();

        // ---- load vf tile into same buffer ----
        for (int idx = t; idx < EE * YT; idx += 256) {
            int e = idx >> 5, y = idx & 31;
            kv[e][y] = (y0 + y < LF) ? g_vf[(size_t)(rowbase + e) * LF + y0 + y]
                                     : make_float2(0.f, 0.f);
        }
        __syncthreads();

        // ---- O-phase: OP += v*sx, OQ += v*sy (packed) ----
        #pragma unroll 4
        for (int y = 0; y < YT; y++) {
            float2 s = sw[y][xo];
            ull sxx = bcast2(s.x);
            ull syy = bcast2(s.y);
            #pragma unroll
            for (int i = 0; i < 8; i++) {
                ull vv = LD64(&kv[eb + i][y]);
                FFMA2ACC(OP[i], vv, sxx);
                FFMA2ACC(OQ[i], vv, syy);
            }
        }
        __syncthreads();
    }

    // ---- combine, normalize, write ----
    const int xg = x0 + xo;
    if (xg < LF) {
        float inv = 1.f / fmaxf(rsum[xo], 1e-12f);
        #pragma unroll
        for (int i = 0; i < 8; i++) {
            float ox = OP[i].x - OQ[i].y;     // sx*vx - sy*vy
            float oy = OP[i].y + OQ[i].x;     // sx*vy + sy*vx
            g_of[(size_t)(rowbase + eb + i) * LF + xg] = make_float2(ox * inv, oy * inv);
        }
    }
}

// ======================================================================
// Kernel 5: irfft (ortho) + scatter to [B,L,H,E]. grid = 8192 rows.
// ======================================================================
__global__ void __launch_bounds__(256) ifft_kernel(float* __restrict__ out)
{
    __shared__ float2 sa[1024];
    __shared__ float2 sb[1024];
    const int row = blockIdx.x;
    const int b = row >> 9, c = row & 511;
    const int tid = threadIdx.x;
    const float2* src = g_of + (size_t)row * LF;

    for (int n = tid; n < 1024; n += 256) {
        if (n <= 512) sa[n] = src[n];
        else {
            float2 v = src[1024 - n];
            sa[n] = make_float2(v.x, -v.y);
        }
    }
    __syncthreads();
    float2* res = fft1024_r4(sa, sb, tid, +1.f);

    float* dst = out + (size_t)b * (LL * DD) + c;
    const float sc = 0.03125f;
    for (int l = tid; l < 1024; l += 256)
        dst[(size_t)l * DD] = res[l].x * sc;
}

// ======================================================================
// launch
// ======================================================================
extern "C" void kernel_launch(void* const* d_in, const int* in_sizes, int n_in,
                              void* d_out, int out_size)
{
    const float* q    = (const float*)d_in[0];
    const float* k    = (const float*)d_in[1];
    const float* v    = (const float*)d_in[2];
    const float* W    = (const float*)d_in[3];
    const float* bias = (const float*)d_in[4];
    float* out = (float*)d_out;

    wtrans_kernel<<<(1536 * 1024 + 255) / 256, 256>>>(W);

    dim3 cg(LL / 128, C2 / 128, BB);
    conv_kernel<<<cg, 256>>>(q, bias);

    fft_q_kernel<<<NROW, 256>>>();
    fft_kv_kernel<<<dim3(NROW, 2), 256>>>(k, v);

    attn_kernel<<<dim3((LF + XT - 1) / XT, BB * HH), 256>>>();

    ifft_kernel<<<NROW, 256>>>(out);
}